// round 6
// baseline (speedup 1.0000x reference)
#include <cuda_runtime.h>
#include <cuda_bf16.h>
#include <cstdint>

// ===========================================================================
// TrainableTree: out[n] = a(x_n) * ( sin(Wt x_n + bt) . w_eff + c )
// Tree after sin() is linear with OUT=1 -> collapses to (w_eff[64], c).
// Kernel 1 (fused): blocks 0-15 compose (w_eff,c); blocks 16+ prepack x into
//   ready-to-use HMMA A-fragments (bf16 hi/lo split) + envelope values.
// Kernel 2 (main): frag LDG -> 16x HMMA -> sin (MUFU+poly mix) -> dot -> out.
// ===========================================================================

#define MAXN      262144
#define MAXCHUNKS (MAXN / 16)

__device__ float g_part[16][64];   // per-leaf partials of w_eff
__device__ float c_part[16];       // per-leaf partials of c
__device__ uint4 g_afrag[MAXCHUNKS * 64];   // [chunk][a0 frags 0-31 | a1 frags 32-63]
__device__ float g_env[MAXN];

// ---------------- helpers ----------------
__device__ __forceinline__ uint32_t bfpk(float lo, float hi) {
    uint32_t d;
    asm("cvt.rn.bf16x2.f32 %0, %1, %2;" : "=r"(d) : "f"(hi), "f"(lo));
    return d;   // lower 16 = bf16(lo), upper 16 = bf16(hi)
}
__device__ __forceinline__ float bflo(uint32_t p) { return __uint_as_float(p << 16); }
__device__ __forceinline__ float bfhi(uint32_t p) { return __uint_as_float(p & 0xffff0000u); }

// ---------------------------------------------------------------------------
// Kernel 1: compose (blocks 0-15) + prepack (blocks 16+). 128 threads.
// ---------------------------------------------------------------------------
__global__ void __launch_bounds__(128)
prep_kernel(const float* __restrict__ x,
            const float* __restrict__ Wleaf, const float* __restrict__ bleaf,
            const float* __restrict__ W3, const float* __restrict__ b3,
            const float* __restrict__ W2, const float* __restrict__ b2,
            const float* __restrict__ W1, const float* __restrict__ b1,
            const float* __restrict__ Wr, const float* __restrict__ br,
            int N, int n_chunks) {
    const int t = threadIdx.x;

    if (blockIdx.x < 16) {
        // ================= compose block k =================
        __shared__ float sGr[64], sG1[64], sG2[64], sG3[64];
        __shared__ float red[2][64];
        __shared__ float cp[64];
        const int k = blockIdx.x;
        const int o = t & 63, q = t >> 6;   // q in {0,1}

        if (t < 64) sGr[t] = Wr[t];
        __syncthreads();

        {   // g1: 2 nodes x 64 outputs = 128 threads, 64 MACs each
            const float* W = W1 + (t >> 6) * 4096;
            float s = 0.f;
            #pragma unroll 8
            for (int p = 0; p < 64; p++) s = fmaf(W[p * 64 + o], sGr[p], s);
            if ((t >> 6) == ((k >> 3) & 1)) sG1[o] = s;   // keep only needed node
        }
        __syncthreads();

        {   // g2: node j = k>>2 (needed one), 2-way split over p
            const float* W = W2 + (k >> 2) * 4096;
            float s = 0.f;
            #pragma unroll 8
            for (int p = q * 32; p < q * 32 + 32; p++) s = fmaf(W[p * 64 + o], sG1[p], s);
            red[q][o] = s;
        }
        __syncthreads();
        if (t < 64) sG2[t] = red[0][t] + red[1][t];
        __syncthreads();

        {   // g3: node m = k>>1
            const float* W = W3 + (k >> 1) * 4096;
            float s = 0.f;
            #pragma unroll 8
            for (int p = q * 32; p < q * 32 + 32; p++) s = fmaf(W[p * 64 + o], sG2[p], s);
            red[q][o] = s;
        }
        __syncthreads();
        if (t < 64) sG3[t] = red[0][t] + red[1][t];
        __syncthreads();

        {   // leaf k: w_eff partial
            const float* W = Wleaf + k * 4096;
            float s = 0.f;
            #pragma unroll 8
            for (int p = q * 32; p < q * 32 + 32; p++) s = fmaf(W[p * 64 + o], sG3[p], s);
            red[q][o] = s;
        }
        __syncthreads();
        if (t < 64) g_part[k][t] = red[0][t] + red[1][t];

        // bias partials (each term counted exactly once across blocks)
        if (t < 64) {
            float s = sG3[o] * bleaf[k * 64 + o];
            if ((k & 1) == 0) s = fmaf(sG2[o], b3[(k >> 1) * 64 + o], s);
            if ((k & 3) == 0) s = fmaf(sG1[o], b2[(k >> 2) * 64 + o], s);
            if (k == 0)       s = fmaf(sGr[o], b1[o] + b1[64 + o], s);
            cp[o] = s;
        }
        __syncthreads();
        if (t == 0) {
            float s = (k == 0) ? br[0] : 0.f;
            #pragma unroll 8
            for (int i = 0; i < 64; i++) s += cp[i];
            c_part[k] = s;
        }
        return;
    }

    // ================= prepack =================
    __shared__ uint32_t sA[4][16][20];    // per warp: 16 rows x 80B
    const int wid = t >> 5, lane = t & 31;
    const int s16 = lane & 15;
    const int lm_sub = lane >> 3, lm_r = lane & 7;
    const int lm_row = lm_r + 8 * (lm_sub & 1);
    const uint32_t lm_base =
        (uint32_t)__cvta_generic_to_shared(&sA[wid][lm_row][0]) + (lm_sub >> 1) * 16;

    const int wglobal = (blockIdx.x - 16) * 4 + wid;
    const int wstride = (gridDim.x - 16) * 4;

    for (int ch = wglobal; ch < n_chunks; ch += wstride) {
        const int row = ch * 16 + s16;
        float xv[10];
        if (row < N) {
            const float2* p = (const float2*)(x + (size_t)row * 10);
            #pragma unroll
            for (int i = 0; i < 5; i++) { float2 v = p[i]; xv[2*i] = v.x; xv[2*i+1] = v.y; }
        } else {
            #pragma unroll
            for (int d = 0; d < 10; d++) xv[d] = 0.f;
        }

        // envelope
        float env = fmaf(xv[0], xv[0], -1.f);
        #pragma unroll
        for (int d = 1; d < 10; d++) env *= fmaf(xv[d], xv[d], -1.f);
        env = env * rsqrtf(fmaf(env, env, 1000.f));
        if (lane < 16 && row < N) g_env[row] = env;

        // stage A row (2 lanes per sample)
        uint32_t H[5];
        #pragma unroll
        for (int j = 0; j < 5; j++) H[j] = bfpk(xv[2 * j], xv[2 * j + 1]);
        uint32_t* arow = sA[wid][s16];
        if (lane < 16) {
            const uint32_t L0 = bfpk(xv[0] - bflo(H[0]), xv[1] - bfhi(H[0]));
            const uint32_t L1 = bfpk(xv[2] - bflo(H[1]), xv[3] - bfhi(H[1]));
            const uint32_t L2 = bfpk(xv[4] - bflo(H[2]), xv[5] - bfhi(H[2]));
            *(uint4*)&arow[0] = make_uint4(H[0], H[1], H[2], H[3]);
            *(uint4*)&arow[4] = make_uint4(H[4], L0, L1, L2);
        } else {
            const uint32_t L3 = bfpk(xv[6] - bflo(H[3]), xv[7] - bfhi(H[3]));
            const uint32_t L4 = bfpk(xv[8] - bflo(H[4]), xv[9] - bfhi(H[4]));
            *(uint4*)&arow[8]  = make_uint4(L3, L4, H[0], H[1]);
            *(uint4*)&arow[12] = make_uint4(H[2], H[3], H[4], 0x3f803f80u); // ones
        }
        __syncwarp();

        uint32_t a0[4], a1[4];
        asm volatile("ldmatrix.sync.aligned.m8n8.x4.shared.b16 {%0,%1,%2,%3}, [%4];"
                     : "=r"(a0[0]), "=r"(a0[1]), "=r"(a0[2]), "=r"(a0[3])
                     : "r"(lm_base));
        asm volatile("ldmatrix.sync.aligned.m8n8.x4.shared.b16 {%0,%1,%2,%3}, [%4];"
                     : "=r"(a1[0]), "=r"(a1[1]), "=r"(a1[2]), "=r"(a1[3])
                     : "r"(lm_base + 32));

        uint4* dst = g_afrag + (size_t)ch * 64 + lane;
        dst[0]  = make_uint4(a0[0], a0[1], a0[2], a0[3]);
        dst[32] = make_uint4(a1[0], a1[1], a1[2], a1[3]);
    }
}

// ---------------------------------------------------------------------------
// Main kernel: lean hot loop. Per warp-iter (16 samples):
//   2x LDG.128 (A frags) + 16 HMMA + sin (12 poly / 20 MUFU) + 32 FFMA dot
//   + lane reduce + env LDG + 2 STG.
// ---------------------------------------------------------------------------
__global__ void __launch_bounds__(128, 8)
tree_main_kernel(const float* __restrict__ Wt, const float* __restrict__ bt,
                 float* __restrict__ out, int N, int n_chunks) {
    __shared__ uint32_t sB[64][18];       // [out][k-pair], 72B rows
    __shared__ float sWeff[64];
    __shared__ float sC[1];

    const int t = threadIdx.x;
    const int wid = t >> 5, lane = t & 31;
    const int c = lane & 3, g = lane >> 2;

    // ---- reduce w_eff / c from compose partials ----
    if (t < 64) {
        float s = 0.f;
        #pragma unroll
        for (int k = 0; k < 16; k++) s += g_part[k][t];
        sWeff[t] = s;
    }
    if (t == 64) {
        float s = 0.f;
        #pragma unroll
        for (int k = 0; k < 16; k++) s += c_part[k];
        sC[0] = s;
    }

    // ---- build B tile (thread t = output t) ----
    if (t < 64) {
        const float2* wr = (const float2*)(Wt + t * 10);
        uint32_t H[5], L[5];
        #pragma unroll
        for (int j = 0; j < 5; j++) {
            const float2 v = wr[j];
            H[j] = bfpk(v.x, v.y);
            L[j] = bfpk(v.x - bflo(H[j]), v.y - bfhi(H[j]));
        }
        const float bv = bt[t];
        const uint32_t bh = bfpk(bv, 0.f);
        const uint32_t bp = bfpk(bv, bv - bflo(bh));   // {bt_hi, bt_lo}
        #pragma unroll
        for (int j = 0; j < 5; j++) {
            sB[t][j]      = H[j];   // k 0-9  : W_hi
            sB[t][5 + j]  = H[j];   // k 10-19: W_hi
            sB[t][10 + j] = L[j];   // k 20-29: W_lo
        }
        sB[t][15] = bp;             // k 30,31: bt_hi, bt_lo
        sB[t][16] = 0u; sB[t][17] = 0u;
    }
    __syncthreads();

    // ---- load B fragments into registers (once) ----
    uint32_t bf0[8][2], bf1[8][2];   // [n-tile][k-chunk]
    #pragma unroll
    for (int nt = 0; nt < 8; nt++) {
        const int row = 8 * nt + g;
        #pragma unroll
        for (int kc = 0; kc < 2; kc++) {
            bf0[nt][kc] = sB[row][kc * 8 + c];
            bf1[nt][kc] = sB[row][kc * 8 + 4 + c];
        }
    }
    const float cv = sC[0];

    const float C7f = -1.9841270e-4f, C5f = 8.3333333e-3f, C3f = -1.6666667e-1f;

    const int wglobal = blockIdx.x * 4 + wid;
    const int wstride = gridDim.x * 4;

    for (int ch = wglobal; ch < n_chunks; ch += wstride) {
        const uint4* src = g_afrag + (size_t)ch * 64 + lane;
        const uint4 A0 = src[0];
        const uint4 A1 = src[32];

        // env load for output lanes
        const int base = ch * 16;
        const int erow = base + g + ((c == 1) ? 8 : 0);
        float env = 0.f;
        if (c < 2 && erow < N) env = g_env[erow];

        float accA = 0.f, accB = 0.f;
        #pragma unroll
        for (int nt = 0; nt < 8; nt++) {
            float d0 = 0.f, d1 = 0.f, d2 = 0.f, d3 = 0.f;
            asm volatile(
                "mma.sync.aligned.m16n8k16.row.col.f32.bf16.bf16.f32 "
                "{%0,%1,%2,%3}, {%4,%5,%6,%7}, {%8,%9}, {%0,%1,%2,%3};"
                : "+f"(d0), "+f"(d1), "+f"(d2), "+f"(d3)
                : "r"(A0.x), "r"(A0.y), "r"(A0.z), "r"(A0.w),
                  "r"(bf0[nt][0]), "r"(bf1[nt][0]));
            asm volatile(
                "mma.sync.aligned.m16n8k16.row.col.f32.bf16.bf16.f32 "
                "{%0,%1,%2,%3}, {%4,%5,%6,%7}, {%8,%9}, {%0,%1,%2,%3};"
                : "+f"(d0), "+f"(d1), "+f"(d2), "+f"(d3)
                : "r"(A1.x), "r"(A1.y), "r"(A1.z), "r"(A1.w),
                  "r"(bf0[nt][1]), "r"(bf1[nt][1]));

            const float2 wv = *(const float2*)&sWeff[8 * nt + 2 * c];
            float s0, s1v, s2v, s3v;
            if (nt < 3) {
                // polynomial sin (offloads the MUFU port)
                float t2;
                t2 = d0 * d0;
                s0 = fmaf(t2, C7f, C5f); s0 = fmaf(t2, s0, C3f);
                s0 = d0 * fmaf(t2, s0, 1.f);
                t2 = d1 * d1;
                s1v = fmaf(t2, C7f, C5f); s1v = fmaf(t2, s1v, C3f);
                s1v = d1 * fmaf(t2, s1v, 1.f);
                t2 = d2 * d2;
                s2v = fmaf(t2, C7f, C5f); s2v = fmaf(t2, s2v, C3f);
                s2v = d2 * fmaf(t2, s2v, 1.f);
                t2 = d3 * d3;
                s3v = fmaf(t2, C7f, C5f); s3v = fmaf(t2, s3v, C3f);
                s3v = d3 * fmaf(t2, s3v, 1.f);
            } else {
                asm("sin.approx.f32 %0, %1;" : "=f"(s0)  : "f"(d0));
                asm("sin.approx.f32 %0, %1;" : "=f"(s1v) : "f"(d1));
                asm("sin.approx.f32 %0, %1;" : "=f"(s2v) : "f"(d2));
                asm("sin.approx.f32 %0, %1;" : "=f"(s3v) : "f"(d3));
            }
            accA = fmaf(s0,  wv.x, accA);
            accA = fmaf(s1v, wv.y, accA);
            accB = fmaf(s2v, wv.x, accB);
            accB = fmaf(s3v, wv.y, accB);
        }

        // reduce over the 4 lanes (c=0..3) sharing the same sample rows
        accA += __shfl_xor_sync(0xffffffffu, accA, 1);
        accA += __shfl_xor_sync(0xffffffffu, accA, 2);
        accB += __shfl_xor_sync(0xffffffffu, accB, 1);
        accB += __shfl_xor_sync(0xffffffffu, accB, 2);

        if (c == 0 && base + g < N)     out[base + g]     = env * (accA + cv);
        if (c == 1 && base + g + 8 < N) out[base + g + 8] = env * (accB + cv);
    }
}

// ---------------------------------------------------------------------------
extern "C" void kernel_launch(void* const* d_in, const int* in_sizes, int n_in,
                              void* d_out, int out_size) {
    const float* x     = (const float*)d_in[0];
    const float* Wt    = (const float*)d_in[1];
    const float* bt    = (const float*)d_in[2];
    const float* Wleaf = (const float*)d_in[3];
    const float* bleaf = (const float*)d_in[4];
    const float* W3    = (const float*)d_in[5];
    const float* b3    = (const float*)d_in[6];
    const float* W2    = (const float*)d_in[7];
    const float* b2    = (const float*)d_in[8];
    const float* W1    = (const float*)d_in[9];
    const float* b1    = (const float*)d_in[10];
    const float* Wr    = (const float*)d_in[11];
    const float* br    = (const float*)d_in[12];
    float* out = (float*)d_out;

    int N = in_sizes[0] / 10;
    if (N > MAXN) N = MAXN;
    const int n_chunks = (N + 15) / 16;

    // Kernel 1: 16 compose blocks + prepack blocks
    int pgrid = 1024;
    int pmax = (n_chunks + 3) / 4;
    if (pgrid > pmax) pgrid = pmax;
    prep_kernel<<<16 + pgrid, 128>>>(x, Wleaf, bleaf, W3, b3, W2, b2,
                                     W1, b1, Wr, br, N, n_chunks);

    // Kernel 2: main
    int grid = 1024;
    int gmax = (n_chunks + 3) / 4;
    if (grid > gmax) grid = gmax;
    tree_main_kernel<<<grid, 128>>>(Wt, bt, out, N, n_chunks);
}

// round 7
// speedup vs baseline: 1.1981x; 1.1981x over previous
#include <cuda_runtime.h>
#include <cuda_bf16.h>
#include <cstdint>

// ===========================================================================
// TrainableTree: out[n] = a(x_n) * ( sin(Wt x_n + bt) . w_eff + c )
// Tree after sin() is linear with OUT=1 -> collapses to (w_eff[64], c).
// compose_kernel: 16 blocks, weights register-resident (one latency round).
// tree_main_kernel: fused staging -> HMMA (bf16 hi/lo split) -> sin -> dot,
//   with next-chunk x prefetched under the epilogue.
// ===========================================================================

__device__ float g_part[16][64];   // per-leaf partials of w_eff
__device__ float c_part[16];       // per-leaf partials of c

// ---------------- helpers ----------------
__device__ __forceinline__ uint32_t bfpk(float lo, float hi) {
    uint32_t d;
    asm("cvt.rn.bf16x2.f32 %0, %1, %2;" : "=r"(d) : "f"(hi), "f"(lo));
    return d;   // lower 16 = bf16(lo), upper 16 = bf16(hi)
}
__device__ __forceinline__ float bflo(uint32_t p) { return __uint_as_float(p << 16); }
__device__ __forceinline__ float bfhi(uint32_t p) { return __uint_as_float(p & 0xffff0000u); }

// ---------------------------------------------------------------------------
// Compose: 16 blocks x 256 thr. Block k needs W1[k>>3], W2[k>>2], W3[k>>1],
// Wleaf[k]. All weight slices loaded into REGISTERS up front (independent
// loads, single DRAM latency round), then the 4-stage chain is smem/FMA only.
// ---------------------------------------------------------------------------
__global__ void __launch_bounds__(256)
compose_kernel(const float* __restrict__ Wleaf, const float* __restrict__ bleaf,
               const float* __restrict__ W3, const float* __restrict__ b3,
               const float* __restrict__ W2, const float* __restrict__ b2,
               const float* __restrict__ W1, const float* __restrict__ b1,
               const float* __restrict__ Wr, const float* __restrict__ br) {
    __shared__ float sGr[64], sG1[64], sG2[64], sG3[64];
    __shared__ float red[4][64];
    __shared__ float cp[64];

    const int t = threadIdx.x;
    const int k = blockIdx.x;
    const int o = t & 63, q = t >> 6;   // q in 0..3
    const int p0 = q * 16;

    // ---- issue ALL loads up front (independent; one latency round) ----
    const float* W1n = W1 + (k >> 3) * 4096;
    const float* W2n = W2 + (k >> 2) * 4096;
    const float* W3n = W3 + (k >> 1) * 4096;
    const float* WLn = Wleaf + k * 4096;
    float w1r[16], w2r[16], w3r[16], wlr[16];
    #pragma unroll
    for (int i = 0; i < 16; i++) w1r[i] = W1n[(p0 + i) * 64 + o];
    #pragma unroll
    for (int i = 0; i < 16; i++) w2r[i] = W2n[(p0 + i) * 64 + o];
    #pragma unroll
    for (int i = 0; i < 16; i++) w3r[i] = W3n[(p0 + i) * 64 + o];
    #pragma unroll
    for (int i = 0; i < 16; i++) wlr[i] = WLn[(p0 + i) * 64 + o];

    const float blf = bleaf[k * 64 + o];
    const float b3v = ((k & 1) == 0) ? b3[(k >> 1) * 64 + o] : 0.f;
    const float b2v = ((k & 3) == 0) ? b2[(k >> 2) * 64 + o] : 0.f;
    const float b1v = (k == 0) ? (b1[o] + b1[64 + o]) : 0.f;

    if (t < 64) sGr[t] = Wr[t];
    __syncthreads();

    // stage 1: g1 = gr . W1n
    {
        float s = 0.f;
        #pragma unroll
        for (int i = 0; i < 16; i++) s = fmaf(w1r[i], sGr[p0 + i], s);
        red[q][o] = s;
    }
    __syncthreads();
    if (t < 64) sG1[t] = red[0][t] + red[1][t] + red[2][t] + red[3][t];
    __syncthreads();

    // stage 2
    {
        float s = 0.f;
        #pragma unroll
        for (int i = 0; i < 16; i++) s = fmaf(w2r[i], sG1[p0 + i], s);
        red[q][o] = s;
    }
    __syncthreads();
    if (t < 64) sG2[t] = red[0][t] + red[1][t] + red[2][t] + red[3][t];
    __syncthreads();

    // stage 3
    {
        float s = 0.f;
        #pragma unroll
        for (int i = 0; i < 16; i++) s = fmaf(w3r[i], sG2[p0 + i], s);
        red[q][o] = s;
    }
    __syncthreads();
    if (t < 64) sG3[t] = red[0][t] + red[1][t] + red[2][t] + red[3][t];
    __syncthreads();

    // stage 4: leaf
    {
        float s = 0.f;
        #pragma unroll
        for (int i = 0; i < 16; i++) s = fmaf(wlr[i], sG3[p0 + i], s);
        red[q][o] = s;
    }
    __syncthreads();
    if (t < 64) g_part[k][t] = red[0][t] + red[1][t] + red[2][t] + red[3][t];

    // bias partials (each term counted once across blocks)
    if (t < 64) {
        float s = sG3[o] * blf;
        s = fmaf(sG2[o], b3v, s);
        s = fmaf(sG1[o], b2v, s);
        s = fmaf(sGr[o], b1v, s);
        cp[o] = s;
    }
    __syncthreads();
    if (t == 0) {
        float s = (k == 0) ? br[0] : 0.f;
        #pragma unroll 8
        for (int i = 0; i < 64; i++) s += cp[i];
        c_part[k] = s;
    }
}

// ---------------------------------------------------------------------------
// Main kernel. Per warp-iteration: 16 samples.
//   A (x) tile: 16 rows x 32 K bf16 in smem (80B rows, conflict-free ldmatrix)
//   K cols: [x_hi(10) | x_lo(10) | x_hi(10) | 1, 1]
//   B cols: [W_hi(10) | W_hi(10) | W_lo(10) | bt_hi, bt_lo]
//   h = x_hi.W_hi + x_lo.W_hi + x_hi.W_lo + bt   (fp32 accum, ~1e-5 rel)
//   Next chunk's x prefetched right after ldmatrix (hidden under MMA+sin).
// ---------------------------------------------------------------------------
__global__ void __launch_bounds__(128, 6)
tree_main_kernel(const float* __restrict__ x, const float* __restrict__ Wt,
                 const float* __restrict__ bt, float* __restrict__ out,
                 int N, int n_chunks) {
    __shared__ uint32_t sB[64][18];       // [out][k-pair], 72B rows
    __shared__ uint32_t sA[4][16][20];    // per warp: 16 rows x 80B
    __shared__ float sWeff[64];
    __shared__ float sC[1];

    const int t = threadIdx.x;
    const int wid = t >> 5, lane = t & 31;
    const int c = lane & 3, g = lane >> 2;

    // ---- reduce w_eff / c from compose partials ----
    if (t < 64) {
        float s = 0.f;
        #pragma unroll
        for (int k = 0; k < 16; k++) s += g_part[k][t];
        sWeff[t] = s;
    }
    if (t == 64) {
        float s = 0.f;
        #pragma unroll
        for (int k = 0; k < 16; k++) s += c_part[k];
        sC[0] = s;
    }

    // ---- build B tile (thread t = output t) ----
    if (t < 64) {
        const float2* wr = (const float2*)(Wt + t * 10);
        uint32_t H[5], L[5];
        #pragma unroll
        for (int j = 0; j < 5; j++) {
            const float2 v = wr[j];
            H[j] = bfpk(v.x, v.y);
            L[j] = bfpk(v.x - bflo(H[j]), v.y - bfhi(H[j]));
        }
        const float bv = bt[t];
        const uint32_t bh = bfpk(bv, 0.f);
        const uint32_t bp = bfpk(bv, bv - bflo(bh));   // {bt_hi, bt_lo}
        #pragma unroll
        for (int j = 0; j < 5; j++) {
            sB[t][j]      = H[j];   // k 0-9  : W_hi
            sB[t][5 + j]  = H[j];   // k 10-19: W_hi
            sB[t][10 + j] = L[j];   // k 20-29: W_lo
        }
        sB[t][15] = bp;             // k 30,31: bt_hi, bt_lo
        sB[t][16] = 0u; sB[t][17] = 0u;
    }
    __syncthreads();

    // ---- load B fragments into registers (once) ----
    uint32_t bf0[8][2], bf1[8][2];   // [n-tile][k-chunk]
    #pragma unroll
    for (int nt = 0; nt < 8; nt++) {
        const int row = 8 * nt + g;
        #pragma unroll
        for (int kc = 0; kc < 2; kc++) {
            bf0[nt][kc] = sB[row][kc * 8 + c];
            bf1[nt][kc] = sB[row][kc * 8 + 4 + c];
        }
    }
    const float cv = sC[0];

    const int s16 = lane & 15;
    const int lm_sub = lane >> 3, lm_r = lane & 7;
    const int lm_row = lm_r + 8 * (lm_sub & 1);
    const uint32_t lm_base =
        (uint32_t)__cvta_generic_to_shared(&sA[wid][lm_row][0]) + (lm_sub >> 1) * 16;

    const float C7f = -1.9841270e-4f, C5f = 8.3333333e-3f, C3f = -1.6666667e-1f;

    const int wglobal = blockIdx.x * 4 + wid;
    const int wstride = gridDim.x * 4;

    // ---- prologue: load first chunk's x ----
    float xv[10];
    {
        const int row = wglobal * 16 + s16;
        if (wglobal < n_chunks && row < N) {
            const float2* p = (const float2*)(x + (size_t)row * 10);
            #pragma unroll
            for (int i = 0; i < 5; i++) { float2 v = p[i]; xv[2*i] = v.x; xv[2*i+1] = v.y; }
        } else {
            #pragma unroll
            for (int d = 0; d < 10; d++) xv[d] = 0.f;
        }
    }

    for (int ch = wglobal; ch < n_chunks; ch += wstride) {
        // envelope
        float env = fmaf(xv[0], xv[0], -1.f);
        #pragma unroll
        for (int d = 1; d < 10; d++) env *= fmaf(xv[d], xv[d], -1.f);
        env = env * rsqrtf(fmaf(env, env, 1000.f));

        // stage A row (2 lanes per sample; lane<16: k-pairs 0-7, else 8-15)
        uint32_t H[5];
        #pragma unroll
        for (int j = 0; j < 5; j++) H[j] = bfpk(xv[2 * j], xv[2 * j + 1]);
        uint32_t* arow = sA[wid][s16];
        if (lane < 16) {
            const uint32_t L0 = bfpk(xv[0] - bflo(H[0]), xv[1] - bfhi(H[0]));
            const uint32_t L1 = bfpk(xv[2] - bflo(H[1]), xv[3] - bfhi(H[1]));
            const uint32_t L2 = bfpk(xv[4] - bflo(H[2]), xv[5] - bfhi(H[2]));
            *(uint4*)&arow[0] = make_uint4(H[0], H[1], H[2], H[3]);
            *(uint4*)&arow[4] = make_uint4(H[4], L0, L1, L2);
        } else {
            const uint32_t L3 = bfpk(xv[6] - bflo(H[3]), xv[7] - bfhi(H[3]));
            const uint32_t L4 = bfpk(xv[8] - bflo(H[4]), xv[9] - bfhi(H[4]));
            *(uint4*)&arow[8]  = make_uint4(L3, L4, H[0], H[1]);
            *(uint4*)&arow[12] = make_uint4(H[2], H[3], H[4], 0x3f803f80u); // ones
        }
        __syncwarp();

        uint32_t a0[4], a1[4];
        asm volatile("ldmatrix.sync.aligned.m8n8.x4.shared.b16 {%0,%1,%2,%3}, [%4];"
                     : "=r"(a0[0]), "=r"(a0[1]), "=r"(a0[2]), "=r"(a0[3])
                     : "r"(lm_base));
        asm volatile("ldmatrix.sync.aligned.m8n8.x4.shared.b16 {%0,%1,%2,%3}, [%4];"
                     : "=r"(a1[0]), "=r"(a1[1]), "=r"(a1[2]), "=r"(a1[3])
                     : "r"(lm_base + 32));

        // ---- prefetch next chunk's x (hidden under MMA + sin + dot) ----
        const int nch = ch + wstride;
        {
            const int row = nch * 16 + s16;
            if (nch < n_chunks && row < N) {
                const float2* p = (const float2*)(x + (size_t)row * 10);
                #pragma unroll
                for (int i = 0; i < 5; i++) { float2 v = p[i]; xv[2*i] = v.x; xv[2*i+1] = v.y; }
            } else {
                #pragma unroll
                for (int d = 0; d < 10; d++) xv[d] = 0.f;
            }
        }

        float accA = 0.f, accB = 0.f;
        #pragma unroll
        for (int nt = 0; nt < 8; nt++) {
            float d0 = 0.f, d1 = 0.f, d2 = 0.f, d3 = 0.f;
            asm volatile(
                "mma.sync.aligned.m16n8k16.row.col.f32.bf16.bf16.f32 "
                "{%0,%1,%2,%3}, {%4,%5,%6,%7}, {%8,%9}, {%0,%1,%2,%3};"
                : "+f"(d0), "+f"(d1), "+f"(d2), "+f"(d3)
                : "r"(a0[0]), "r"(a0[1]), "r"(a0[2]), "r"(a0[3]),
                  "r"(bf0[nt][0]), "r"(bf1[nt][0]));
            asm volatile(
                "mma.sync.aligned.m16n8k16.row.col.f32.bf16.bf16.f32 "
                "{%0,%1,%2,%3}, {%4,%5,%6,%7}, {%8,%9}, {%0,%1,%2,%3};"
                : "+f"(d0), "+f"(d1), "+f"(d2), "+f"(d3)
                : "r"(a1[0]), "r"(a1[1]), "r"(a1[2]), "r"(a1[3]),
                  "r"(bf0[nt][1]), "r"(bf1[nt][1]));

            const float2 wv = *(const float2*)&sWeff[8 * nt + 2 * c];
            float s0, s1v, s2v, s3v;
            if (nt < 3) {
                // polynomial sin (offloads the MUFU port)
                float t2;
                t2 = d0 * d0;
                s0 = fmaf(t2, C7f, C5f); s0 = fmaf(t2, s0, C3f);
                s0 = d0 * fmaf(t2, s0, 1.f);
                t2 = d1 * d1;
                s1v = fmaf(t2, C7f, C5f); s1v = fmaf(t2, s1v, C3f);
                s1v = d1 * fmaf(t2, s1v, 1.f);
                t2 = d2 * d2;
                s2v = fmaf(t2, C7f, C5f); s2v = fmaf(t2, s2v, C3f);
                s2v = d2 * fmaf(t2, s2v, 1.f);
                t2 = d3 * d3;
                s3v = fmaf(t2, C7f, C5f); s3v = fmaf(t2, s3v, C3f);
                s3v = d3 * fmaf(t2, s3v, 1.f);
            } else {
                asm("sin.approx.f32 %0, %1;" : "=f"(s0)  : "f"(d0));
                asm("sin.approx.f32 %0, %1;" : "=f"(s1v) : "f"(d1));
                asm("sin.approx.f32 %0, %1;" : "=f"(s2v) : "f"(d2));
                asm("sin.approx.f32 %0, %1;" : "=f"(s3v) : "f"(d3));
            }
            accA = fmaf(s0,  wv.x, accA);
            accA = fmaf(s1v, wv.y, accA);
            accB = fmaf(s2v, wv.x, accB);
            accB = fmaf(s3v, wv.y, accB);
        }

        // reduce over the 4 lanes (c=0..3) sharing the same sample rows
        accA += __shfl_xor_sync(0xffffffffu, accA, 1);
        accA += __shfl_xor_sync(0xffffffffu, accA, 2);
        accB += __shfl_xor_sync(0xffffffffu, accB, 1);
        accB += __shfl_xor_sync(0xffffffffu, accB, 2);

        const float envG  = __shfl_sync(0xffffffffu, env, g);
        const float envG8 = __shfl_sync(0xffffffffu, env, g + 8);

        const int base = ch * 16;
        if (c == 0 && base + g < N)     out[base + g]     = envG  * (accA + cv);
        if (c == 1 && base + g + 8 < N) out[base + g + 8] = envG8 * (accB + cv);
    }
}

// ---------------------------------------------------------------------------
extern "C" void kernel_launch(void* const* d_in, const int* in_sizes, int n_in,
                              void* d_out, int out_size) {
    const float* x     = (const float*)d_in[0];
    const float* Wt    = (const float*)d_in[1];
    const float* bt    = (const float*)d_in[2];
    const float* Wleaf = (const float*)d_in[3];
    const float* bleaf = (const float*)d_in[4];
    const float* W3    = (const float*)d_in[5];
    const float* b3    = (const float*)d_in[6];
    const float* W2    = (const float*)d_in[7];
    const float* b2    = (const float*)d_in[8];
    const float* W1    = (const float*)d_in[9];
    const float* b1    = (const float*)d_in[10];
    const float* Wr    = (const float*)d_in[11];
    const float* br    = (const float*)d_in[12];
    float* out = (float*)d_out;

    const int N = in_sizes[0] / 10;
    const int n_chunks = (N + 15) / 16;

    compose_kernel<<<16, 256>>>(Wleaf, bleaf, W3, b3, W2, b2, W1, b1, Wr, br);

    // balanced single wave: capacity 148 SMs x 6 blocks x 4 warps = 3552 warps
    const int cap_warps = 148 * 6 * 4;
    int iters = (n_chunks + cap_warps - 1) / cap_warps;
    int grid = (n_chunks + 4 * iters - 1) / (4 * iters);
    tree_main_kernel<<<grid, 128>>>(x, Wt, bt, out, N, n_chunks);
}